// round 5
// baseline (speedup 1.0000x reference)
#include <cuda_runtime.h>
#include <cuda_bf16.h>
#include <cstdint>

#define NPIX 4096
#define CB   256
#define BQ   4
#define TM   128

// Scratch (device globals — no runtime allocation allowed)
__device__ float g_qk[BQ][64][NPIX];              // rows 0..31 = q, 32..63 = k (tf32)
__device__ __nv_bfloat16 g_kh[BQ][NPIX][32];      // k transposed [m][d], bf16 (1 MB)
__device__ float g_v[BQ][CB][NPIX];               // only when gamma != 0

#define LOG2E 1.4426950408889634f

__device__ __forceinline__ float tf32r(float v) {
    uint32_t u;
    asm("cvt.rna.tf32.f32 %0, %1;" : "=r"(u) : "f"(v));
    return __uint_as_float(u);
}
__device__ __forceinline__ float ex2f(float x) {
    float r;
    asm("ex2.approx.f32 %0, %1;" : "=f"(r) : "f"(x));
    return r;
}

// ---------------------------------------------------------------------------
// Kernel A: q = Wq·sa_D + bq, k = Wk·sa_D + bk
//   -> g_qk[b][d][n] tf32 and g_kh[b][m][d] bf16 (pass-1 source, transposed)
// ---------------------------------------------------------------------------
__global__ void qk_kernel(const float* __restrict__ saD,
                          const float* __restrict__ Wq, const float* __restrict__ bq,
                          const float* __restrict__ Wk, const float* __restrict__ bk)
{
    extern __shared__ float sm[];
    float* sW = sm;                 // 64*258
    float* sX = sm + 64 * 258;      // 64*64
    float* sB = sX + 64 * 64;       // 64

    int b  = blockIdx.y;
    int n0 = blockIdx.x * 64;
    int t  = threadIdx.x;

    for (int i = t; i < 64 * 256; i += 256) {
        int d = i >> 8, c = i & 255;
        sW[d * 258 + c] = (d < 32) ? Wq[d * 256 + c] : Wk[(d - 32) * 256 + c];
    }
    if (t < 64) sB[t] = (t < 32) ? bq[t] : bk[t - 32];
    __syncthreads();

    int ty = t >> 4, tx = t & 15;
    float acc[4][4];
#pragma unroll
    for (int i = 0; i < 4; i++) {
        float bias = sB[ty + 16 * i];
#pragma unroll
        for (int j = 0; j < 4; j++) acc[i][j] = bias;
    }

    for (int c0 = 0; c0 < 256; c0 += 64) {
        __syncthreads();
#pragma unroll
        for (int r = 0; r < 4; r++) {
            int f  = t + 256 * r;
            int cc = f >> 4, nn = (f & 15) << 2;
            *(float4*)&sX[cc * 64 + nn] =
                *(const float4*)&saD[(size_t)(b * 256 + c0 + cc) * NPIX + n0 + nn];
        }
        __syncthreads();
#pragma unroll 4
        for (int cc = 0; cc < 64; cc++) {
            float w0 = sW[(ty     ) * 258 + c0 + cc];
            float w1 = sW[(ty + 16) * 258 + c0 + cc];
            float w2 = sW[(ty + 32) * 258 + c0 + cc];
            float w3 = sW[(ty + 48) * 258 + c0 + cc];
#pragma unroll
            for (int j = 0; j < 4; j++) {
                float x = sX[cc * 64 + tx + 16 * j];
                acc[0][j] += w0 * x; acc[1][j] += w1 * x;
                acc[2][j] += w2 * x; acc[3][j] += w3 * x;
            }
        }
    }
    // tf32 store (q + k)
#pragma unroll
    for (int i = 0; i < 4; i++)
#pragma unroll
        for (int j = 0; j < 4; j++)
            g_qk[b][ty + 16 * i][n0 + tx + 16 * j] = tf32r(acc[i][j]);

    // bf16 transposed k store: stage [n][d] in smem (reuse sX), coalesced out
    __syncthreads();
    __nv_bfloat16* sT = (__nv_bfloat16*)sX;   // 64 x 40 halves
#pragma unroll
    for (int i = 2; i < 4; i++)
#pragma unroll
        for (int j = 0; j < 4; j++)
            sT[(tx + 16 * j) * 40 + ty + 16 * (i - 2)] = __float2bfloat16(acc[i][j]);
    __syncthreads();
    {
        int r = t >> 2, p = t & 3;
        uint4 v = *(uint4*)&sT[r * 40 + p * 8];
        *(uint4*)&g_kh[b][n0 + r][p * 8] = v;
    }
}

// ---------------------------------------------------------------------------
// Kernel B: fused energy + softmax + attention.
// No K staging in smem: B fragments LDG'd straight from L2-resident K with
// register double-buffering. No per-tile barriers. q pre-scaled by log2e so
// exp == raw ex2.approx.
// ---------------------------------------------------------------------------
__device__ __forceinline__ void mma_tf32(float& c0, float& c1, float& c2, float& c3,
                                         const float a[4], float b0, float b1)
{
    asm volatile(
        "mma.sync.aligned.m16n8k8.row.col.f32.tf32.tf32.f32 "
        "{%0,%1,%2,%3}, {%4,%5,%6,%7}, {%8,%9}, {%0,%1,%2,%3};"
        : "+f"(c0), "+f"(c1), "+f"(c2), "+f"(c3)
        : "r"(__float_as_uint(a[0])), "r"(__float_as_uint(a[1])),
          "r"(__float_as_uint(a[2])), "r"(__float_as_uint(a[3])),
          "r"(__float_as_uint(b0)), "r"(__float_as_uint(b1)));
}

__device__ __forceinline__ void mma_bf16(float& c0, float& c1, float& c2, float& c3,
                                         const uint32_t a[4], uint32_t b0, uint32_t b1)
{
    asm volatile(
        "mma.sync.aligned.m16n8k16.row.col.f32.bf16.bf16.f32 "
        "{%0,%1,%2,%3}, {%4,%5,%6,%7}, {%8,%9}, {%0,%1,%2,%3};"
        : "+f"(c0), "+f"(c1), "+f"(c2), "+f"(c3)
        : "r"(a[0]), "r"(a[1]), "r"(a[2]), "r"(a[3]), "r"(b0), "r"(b1));
}

__device__ __forceinline__ uint32_t packbf(float lo, float hi) {
    __nv_bfloat162 h = __floats2bfloat162_rn(lo, hi);
    return *(uint32_t*)&h;
}

__global__ __launch_bounds__(256, 2) void attn_kernel(float* __restrict__ att)
{
    extern __shared__ float sm[];
    float* sQ   = sm;             // 64*33
    float* sSum = sm + 64 * 33;   // 8*64
    float* sInv = sSum + 8 * 64;  // 64

    int b  = blockIdx.y;
    int n0 = blockIdx.x * 64;
    int t  = threadIdx.x, w = t >> 5, l = t & 31;
    int lq = l >> 2, lr = l & 3;
    int j0 = 2 * w;

    const float* qg = &g_qk[b][0][0];
    const float* kg = &g_qk[b][32][0];
    const __nv_bfloat16* khg = &g_kh[b][0][0];

    // Q tile [64 n][32 d], transposed, pre-scaled by log2e
    for (int i = t; i < 64 * 32; i += 256) {
        int n = i & 63, d = i >> 6;
        sQ[n * 33 + d] = qg[(size_t)d * NPIX + n0 + n] * LOG2E;
    }
    __syncthreads();

    // ======== pass 1: bf16 denominators ========
    uint32_t aH[4][2][4];
#pragma unroll
    for (int rg = 0; rg < 4; rg++) {
        int r = rg * 16 + lq;
#pragma unroll
        for (int kk = 0; kk < 2; kk++) {
            int c = kk * 16 + lr * 2;
            aH[rg][kk][0] = packbf(sQ[r * 33 + c],           sQ[r * 33 + c + 1]);
            aH[rg][kk][1] = packbf(sQ[(r + 8) * 33 + c],     sQ[(r + 8) * 33 + c + 1]);
            aH[rg][kk][2] = packbf(sQ[r * 33 + c + 8],       sQ[r * 33 + c + 9]);
            aH[rg][kk][3] = packbf(sQ[(r + 8) * 33 + c + 8], sQ[(r + 8) * 33 + c + 9]);
        }
    }

    // per-(jj) fragment loads: bh[jj][kk][0]=b0, [1]=b1 (each uint32 = 2 halves)
    auto ld_h = [&](int m0, uint32_t bh[2][2][2]) {
#pragma unroll
        for (int jj = 0; jj < 2; jj++) {
            size_t row = (size_t)(m0 + (j0 + jj) * 8 + lq) * 32;
#pragma unroll
            for (int kk = 0; kk < 2; kk++) {
                bh[jj][kk][0] = *(const uint32_t*)&khg[row + kk * 16 + lr * 2];
                bh[jj][kk][1] = *(const uint32_t*)&khg[row + kk * 16 + lr * 2 + 8];
            }
        }
    };

    float s[4][2];
#pragma unroll
    for (int rg = 0; rg < 4; rg++) s[rg][0] = s[rg][1] = 0.f;

    uint32_t bc[2][2][2];
    ld_h(0, bc);
    for (int tile = 0; tile < 32; tile++) {
        uint32_t bn[2][2][2];
        if (tile < 31) ld_h((tile + 1) * TM, bn);
#pragma unroll
        for (int jj = 0; jj < 2; jj++) {
#pragma unroll
            for (int rg = 0; rg < 4; rg++) {
                float c0 = 0.f, c1 = 0.f, c2 = 0.f, c3 = 0.f;
                mma_bf16(c0, c1, c2, c3, aH[rg][0], bc[jj][0][0], bc[jj][0][1]);
                mma_bf16(c0, c1, c2, c3, aH[rg][1], bc[jj][1][0], bc[jj][1][1]);
                s[rg][0] += ex2f(c0) + ex2f(c1);
                s[rg][1] += ex2f(c2) + ex2f(c3);
            }
        }
#pragma unroll
        for (int jj = 0; jj < 2; jj++)
#pragma unroll
            for (int kk = 0; kk < 2; kk++) {
                bc[jj][kk][0] = bn[jj][kk][0];
                bc[jj][kk][1] = bn[jj][kk][1];
            }
    }
#pragma unroll
    for (int rg = 0; rg < 4; rg++)
#pragma unroll
        for (int h = 0; h < 2; h++) {
            s[rg][h] += __shfl_xor_sync(0xffffffffu, s[rg][h], 1);
            s[rg][h] += __shfl_xor_sync(0xffffffffu, s[rg][h], 2);
        }
    if (lr == 0)
#pragma unroll
        for (int rg = 0; rg < 4; rg++) {
            sSum[w * 64 + rg * 16 + lq]     = s[rg][0];
            sSum[w * 64 + rg * 16 + 8 + lq] = s[rg][1];
        }
    __syncthreads();
    if (t < 64) {
        float tot = 0.f;
#pragma unroll
        for (int ww = 0; ww < 8; ww++) tot += sSum[ww * 64 + t];
        sInv[t] = 1.f / tot;
    }
    __syncthreads();

    float inv[4][2];
#pragma unroll
    for (int rg = 0; rg < 4; rg++) {
        inv[rg][0] = sInv[rg * 16 + lq];
        inv[rg][1] = sInv[rg * 16 + 8 + lq];
    }

    // ======== pass 2: tf32 values, direct stores ========
    float aF[4][4][4];
#pragma unroll
    for (int rg = 0; rg < 4; rg++) {
        int r = rg * 16 + lq;
#pragma unroll
        for (int kk = 0; kk < 4; kk++) {
            int c = kk * 8 + lr;
            aF[rg][kk][0] = sQ[r * 33 + c];
            aF[rg][kk][1] = sQ[(r + 8) * 33 + c];
            aF[rg][kk][2] = sQ[r * 33 + c + 4];
            aF[rg][kk][3] = sQ[(r + 8) * 33 + c + 4];
        }
    }

    // fragment loads: bf[jj][kk][0]=b0 (row kk*8+lr), [1]=b1 (row +4)
    auto ld_f = [&](int m0, float bf[2][4][2]) {
#pragma unroll
        for (int jj = 0; jj < 2; jj++) {
            int m = m0 + (j0 + jj) * 8 + lq;
#pragma unroll
            for (int kk = 0; kk < 4; kk++) {
                bf[jj][kk][0] = kg[(size_t)(kk * 8 + lr) * NPIX + m];
                bf[jj][kk][1] = kg[(size_t)(kk * 8 + lr + 4) * NPIX + m];
            }
        }
    };

    float fc[2][4][2];
    ld_f(0, fc);
    for (int tile = 0; tile < 32; tile++) {
        int m0 = tile * TM;
        float fn[2][4][2];
        if (tile < 31) ld_f((tile + 1) * TM, fn);
#pragma unroll
        for (int jj = 0; jj < 2; jj++) {
            int j = j0 + jj;
#pragma unroll
            for (int rg = 0; rg < 4; rg++) {
                float c0 = 0.f, c1 = 0.f, c2 = 0.f, c3 = 0.f;
#pragma unroll
                for (int kk = 0; kk < 4; kk++)
                    mma_tf32(c0, c1, c2, c3, aF[rg][kk], fc[jj][kk][0], fc[jj][kk][1]);
                float p0 = ex2f(c0) * inv[rg][0];
                float p1 = ex2f(c1) * inv[rg][0];
                float p2 = ex2f(c2) * inv[rg][1];
                float p3 = ex2f(c3) * inv[rg][1];
                size_t base = ((size_t)(b * NPIX + n0 + rg * 16 + lq)) * NPIX
                              + m0 + j * 8 + lr * 2;
                *(float2*)&att[base]            = make_float2(p0, p1);
                *(float2*)&att[base + 8 * NPIX] = make_float2(p2, p3);
            }
        }
#pragma unroll
        for (int jj = 0; jj < 2; jj++)
#pragma unroll
            for (int kk = 0; kk < 4; kk++) {
                fc[jj][kk][0] = fn[jj][kk][0];
                fc[jj][kk][1] = fn[jj][kk][1];
            }
    }
}

// ---------------------------------------------------------------------------
// Kernel C: v = Wv·sa_E + bv  (only when gamma != 0 — exact skip otherwise)
// ---------------------------------------------------------------------------
__global__ void v_kernel(const float* __restrict__ saE,
                         const float* __restrict__ Wv,
                         const float* __restrict__ bv,
                         const float* __restrict__ gamma)
{
    if (gamma[0] == 0.f) return;
    int total = BQ * CB * NPIX;
    for (int idx = blockIdx.x * blockDim.x + threadIdx.x; idx < total;
         idx += gridDim.x * blockDim.x) {
        int m  = idx & (NPIX - 1);
        int c  = (idx >> 12) & 255;
        int bb = idx >> 20;
        float s = bv[c];
        for (int cc = 0; cc < 256; cc++)
            s += Wv[c * 256 + cc] * saE[(size_t)(bb * 256 + cc) * NPIX + m];
        g_v[bb][c][m] = s;
    }
}

// ---------------------------------------------------------------------------
// Kernel D: out = gamma*(V·A^T) + sa_E.  gamma==0 -> exact copy (MLP=8)
// ---------------------------------------------------------------------------
__global__ void out_kernel(const float* __restrict__ saE,
                           const float* __restrict__ gamma,
                           float* __restrict__ out,
                           const float* __restrict__ att)
{
    float g = gamma[0];
    const int nvec = (BQ * CB * NPIX) / 4;  // 1048576 float4s
    if (g == 0.f) {
        int i = blockIdx.x * blockDim.x + threadIdx.x;   // 131072 threads
        const int stride = nvec / 8;
        float4 r[8];
#pragma unroll
        for (int k = 0; k < 8; k++) r[k] = ((const float4*)saE)[i + k * stride];
#pragma unroll
        for (int k = 0; k < 8; k++) ((float4*)out)[i + k * stride] = r[k];
    } else {
        for (int i = blockIdx.x * blockDim.x + threadIdx.x; i < nvec;
             i += gridDim.x * blockDim.x) {
            int base = i * 4;
            int n  = base & (NPIX - 1);
            int c  = (base >> 12) & 255;
            int bb = base >> 20;
            float4 e = ((const float4*)saE)[i];
            const float* vrow = &g_v[bb][c][0];
            float rr[4];
#pragma unroll
            for (int jj = 0; jj < 4; jj++) {
                const float* arow = att + (size_t)(bb * NPIX + n + jj) * NPIX;
                float s = 0.f;
                for (int m = 0; m < NPIX; m++) s += vrow[m] * arow[m];
                rr[jj] = g * s + (&e.x)[jj];
            }
            ((float4*)out)[i] = make_float4(rr[0], rr[1], rr[2], rr[3]);
        }
    }
}

// ---------------------------------------------------------------------------
extern "C" void kernel_launch(void* const* d_in, const int* in_sizes, int n_in,
                              void* d_out, int out_size)
{
    const float* saE   = (const float*)d_in[0];
    const float* saD   = (const float*)d_in[1];
    const float* Wq    = (const float*)d_in[2];
    const float* bq    = (const float*)d_in[3];
    const float* Wk    = (const float*)d_in[4];
    const float* bk    = (const float*)d_in[5];
    const float* Wv    = (const float*)d_in[6];
    const float* bv    = (const float*)d_in[7];
    const float* gamma = (const float*)d_in[8];

    float* out = (float*)d_out;
    float* att = out + (size_t)BQ * CB * NPIX;

    size_t smA = (size_t)(64 * 258 + 64 * 64 + 64) * sizeof(float);
    size_t smB = (size_t)(64 * 33 + 8 * 64 + 64) * sizeof(float);
    cudaFuncSetAttribute(qk_kernel,   cudaFuncAttributeMaxDynamicSharedMemorySize, (int)smA);
    cudaFuncSetAttribute(attn_kernel, cudaFuncAttributeMaxDynamicSharedMemorySize, (int)smB);

    qk_kernel<<<dim3(64, 4), 256, smA>>>(saD, Wq, bq, Wk, bk);
    attn_kernel<<<dim3(64, 4), 256, smB>>>(att);
    v_kernel<<<1024, 256>>>(saE, Wv, bv, gamma);
    out_kernel<<<512, 256>>>(saE, gamma, out, att);
}

// round 6
// speedup vs baseline: 1.0925x; 1.0925x over previous
#include <cuda_runtime.h>
#include <cuda_fp16.h>
#include <cstdint>

#define NPIX 4096
#define CB   256
#define BQ   4
#define TM   128
#define SKH  40    // fp16 K-tile stride in halves (conflict-free)

// Scratch (device globals — no runtime allocation allowed)
__device__ float  g_qk[BQ][32][NPIX];        // q (float), [d][n]
__device__ __half g_kh[BQ][NPIX][32];        // k transposed [m][d], fp16 (1 MB)
__device__ float  g_v[BQ][CB][NPIX];         // only when gamma != 0

#define LOG2E 1.4426950408889634f

__device__ __forceinline__ float ex2f(float x) {
    float r;
    asm("ex2.approx.f32 %0, %1;" : "=f"(r) : "f"(x));
    return r;
}

__device__ __forceinline__ void cpasync16(void* smem_dst, const void* gsrc) {
    uint32_t s = (uint32_t)__cvta_generic_to_shared(smem_dst);
    asm volatile("cp.async.cg.shared.global [%0], [%1], 16;" :: "r"(s), "l"(gsrc));
}
#define CP_COMMIT() asm volatile("cp.async.commit_group;" ::: "memory")
#define CP_WAIT0()  asm volatile("cp.async.wait_group 0;" ::: "memory")

// ---------------------------------------------------------------------------
// Kernel A: q = Wq·sa_D + bq (float, [d][n]), k = Wk·sa_D + bk (fp16, [m][d])
// ---------------------------------------------------------------------------
__global__ void qk_kernel(const float* __restrict__ saD,
                          const float* __restrict__ Wq, const float* __restrict__ bq,
                          const float* __restrict__ Wk, const float* __restrict__ bk)
{
    extern __shared__ float sm[];
    float* sW = sm;                 // 64*258
    float* sX = sm + 64 * 258;      // 64*64
    float* sB = sX + 64 * 64;       // 64

    int b  = blockIdx.y;
    int n0 = blockIdx.x * 64;
    int t  = threadIdx.x;

    for (int i = t; i < 64 * 256; i += 256) {
        int d = i >> 8, c = i & 255;
        sW[d * 258 + c] = (d < 32) ? Wq[d * 256 + c] : Wk[(d - 32) * 256 + c];
    }
    if (t < 64) sB[t] = (t < 32) ? bq[t] : bk[t - 32];
    __syncthreads();

    int ty = t >> 4, tx = t & 15;
    float acc[4][4];
#pragma unroll
    for (int i = 0; i < 4; i++) {
        float bias = sB[ty + 16 * i];
#pragma unroll
        for (int j = 0; j < 4; j++) acc[i][j] = bias;
    }

    for (int c0 = 0; c0 < 256; c0 += 64) {
        __syncthreads();
#pragma unroll
        for (int r = 0; r < 4; r++) {
            int f  = t + 256 * r;
            int cc = f >> 4, nn = (f & 15) << 2;
            *(float4*)&sX[cc * 64 + nn] =
                *(const float4*)&saD[(size_t)(b * 256 + c0 + cc) * NPIX + n0 + nn];
        }
        __syncthreads();
#pragma unroll 4
        for (int cc = 0; cc < 64; cc++) {
            float w0 = sW[(ty     ) * 258 + c0 + cc];
            float w1 = sW[(ty + 16) * 258 + c0 + cc];
            float w2 = sW[(ty + 32) * 258 + c0 + cc];
            float w3 = sW[(ty + 48) * 258 + c0 + cc];
#pragma unroll
            for (int j = 0; j < 4; j++) {
                float x = sX[cc * 64 + tx + 16 * j];
                acc[0][j] += w0 * x; acc[1][j] += w1 * x;
                acc[2][j] += w2 * x; acc[3][j] += w3 * x;
            }
        }
    }
    // q store (float)
#pragma unroll
    for (int i = 0; i < 2; i++)
#pragma unroll
        for (int j = 0; j < 4; j++)
            g_qk[b][ty + 16 * i][n0 + tx + 16 * j] = acc[i][j];

    // fp16 transposed k store: stage [n][d] in smem (reuse sX), coalesced out
    __syncthreads();
    __half* sT = (__half*)sX;   // 64 x SKH halves
#pragma unroll
    for (int i = 2; i < 4; i++)
#pragma unroll
        for (int j = 0; j < 4; j++)
            sT[(tx + 16 * j) * SKH + ty + 16 * (i - 2)] = __float2half(acc[i][j]);
    __syncthreads();
    {
        int r = t >> 2, p = t & 3;
        uint4 v = *(uint4*)&sT[r * SKH + p * 8];
        *(uint4*)&g_kh[b][n0 + r][p * 8] = v;
    }
}

// ---------------------------------------------------------------------------
// Kernel B: fused energy + softmax + attention, fp16 m16n8k16 both passes.
// cp.async double-buffered fp16 K tiles (8KB), conflict-free SKH=40 stride.
// Pass 1: h2exp2 (f16x2 MUFU) denominators; pass 2: f32 ex2 values + stores.
// ---------------------------------------------------------------------------
__device__ __forceinline__ void mma_f16(float& c0, float& c1, float& c2, float& c3,
                                        const uint32_t a[4], uint32_t b0, uint32_t b1)
{
    asm volatile(
        "mma.sync.aligned.m16n8k16.row.col.f32.f16.f16.f32 "
        "{%0,%1,%2,%3}, {%4,%5,%6,%7}, {%8,%9}, {%0,%1,%2,%3};"
        : "+f"(c0), "+f"(c1), "+f"(c2), "+f"(c3)
        : "r"(a[0]), "r"(a[1]), "r"(a[2]), "r"(a[3]), "r"(b0), "r"(b1));
}

__device__ __forceinline__ uint32_t packh(float lo, float hi) {
    __half2 h = __floats2half2_rn(lo, hi);
    return *(uint32_t*)&h;
}

__global__ __launch_bounds__(256, 2) void attn_kernel(float* __restrict__ att)
{
    extern __shared__ float sm[];
    float*  sQ   = sm;                            // 64*33 floats
    __half* sKh0 = (__half*)(sm + 64 * 33);       // 128*SKH halves
    __half* sKh1 = sKh0 + 128 * SKH;              // 128*SKH halves
    float*  sSum = (float*)(sKh1 + 128 * SKH);    // 8*64
    float*  sInv = sSum + 8 * 64;                 // 64

    int b  = blockIdx.y;
    int n0 = blockIdx.x * 64;
    int t  = threadIdx.x, w = t >> 5, l = t & 31;
    int lq = l >> 2, lr = l & 3;
    int j0 = 2 * w;

    const float*  qg  = &g_qk[b][0][0];
    const __half* khg = &g_kh[b][0][0];

    // Q tile [64 n][32 d], transposed, pre-scaled by log2e
    for (int i = t; i < 64 * 32; i += 256) {
        int n = i & 63, d = i >> 6;
        sQ[n * 33 + d] = qg[(size_t)d * NPIX + n0 + n] * LOG2E;
    }
    __syncthreads();

    // A fragments fp16: 4 row-groups x 2 k16-chunks x 4 regs
    uint32_t aH[4][2][4];
#pragma unroll
    for (int rg = 0; rg < 4; rg++) {
        int r = rg * 16 + lq;
#pragma unroll
        for (int kk = 0; kk < 2; kk++) {
            int c = kk * 16 + lr * 2;
            aH[rg][kk][0] = packh(sQ[r * 33 + c],           sQ[r * 33 + c + 1]);
            aH[rg][kk][1] = packh(sQ[(r + 8) * 33 + c],     sQ[(r + 8) * 33 + c + 1]);
            aH[rg][kk][2] = packh(sQ[r * 33 + c + 8],       sQ[r * 33 + c + 9]);
            aH[rg][kk][3] = packh(sQ[(r + 8) * 33 + c + 8], sQ[(r + 8) * 33 + c + 9]);
        }
    }

    // cooperative fp16 K tile copy: 128 rows x 32 halves (8KB), 2x16B/thread
    auto cp_tile = [&](int m0, __half* dst) {
#pragma unroll
        for (int r = 0; r < 2; r++) {
            int f = t + 256 * r;                 // 0..511 16B chunks
            int m = f >> 2, p = f & 3;
            cpasync16(&dst[m * SKH + p * 8], &khg[(size_t)(m0 + m) * 32 + p * 8]);
        }
        CP_COMMIT();
    };

    // ======== pass 1: denominators via f16x2 exp2 ========
    float s[4][2];
#pragma unroll
    for (int rg = 0; rg < 4; rg++) s[rg][0] = s[rg][1] = 0.f;

    cp_tile(0, sKh0);
    for (int tile = 0; tile < 32; tile++) {
        __half* cur = (tile & 1) ? sKh1 : sKh0;
        __half* nxt = (tile & 1) ? sKh0 : sKh1;
        CP_WAIT0();
        __syncthreads();
        if (tile < 31) cp_tile((tile + 1) * TM, nxt);

        __half2 ha[4][2];
#pragma unroll
        for (int rg = 0; rg < 4; rg++) {
            ha[rg][0] = __floats2half2_rn(0.f, 0.f);
            ha[rg][1] = __floats2half2_rn(0.f, 0.f);
        }
#pragma unroll
        for (int jj = 0; jj < 2; jj++) {
            int j = j0 + jj;
            uint32_t b0[2], b1[2];
#pragma unroll
            for (int kk = 0; kk < 2; kk++) {
                b0[kk] = *(uint32_t*)&cur[(j * 8 + lq) * SKH + kk * 16 + lr * 2];
                b1[kk] = *(uint32_t*)&cur[(j * 8 + lq) * SKH + kk * 16 + lr * 2 + 8];
            }
#pragma unroll
            for (int rg = 0; rg < 4; rg++) {
                float c0 = 0.f, c1 = 0.f, c2 = 0.f, c3 = 0.f;
                mma_f16(c0, c1, c2, c3, aH[rg][0], b0[0], b1[0]);
                mma_f16(c0, c1, c2, c3, aH[rg][1], b0[1], b1[1]);
                ha[rg][0] = __hadd2(ha[rg][0], h2exp2(__floats2half2_rn(c0, c1)));
                ha[rg][1] = __hadd2(ha[rg][1], h2exp2(__floats2half2_rn(c2, c3)));
            }
        }
#pragma unroll
        for (int rg = 0; rg < 4; rg++) {
            float2 f0 = __half22float2(ha[rg][0]);
            float2 f1 = __half22float2(ha[rg][1]);
            s[rg][0] += f0.x + f0.y;
            s[rg][1] += f1.x + f1.y;
        }
        __syncthreads();
    }
#pragma unroll
    for (int rg = 0; rg < 4; rg++)
#pragma unroll
        for (int h = 0; h < 2; h++) {
            s[rg][h] += __shfl_xor_sync(0xffffffffu, s[rg][h], 1);
            s[rg][h] += __shfl_xor_sync(0xffffffffu, s[rg][h], 2);
        }
    if (lr == 0)
#pragma unroll
        for (int rg = 0; rg < 4; rg++) {
            sSum[w * 64 + rg * 16 + lq]     = s[rg][0];
            sSum[w * 64 + rg * 16 + 8 + lq] = s[rg][1];
        }
    __syncthreads();
    if (t < 64) {
        float tot = 0.f;
#pragma unroll
        for (int ww = 0; ww < 8; ww++) tot += sSum[ww * 64 + t];
        sInv[t] = 1.f / tot;
    }
    __syncthreads();

    float inv[4][2];
#pragma unroll
    for (int rg = 0; rg < 4; rg++) {
        inv[rg][0] = sInv[rg * 16 + lq];
        inv[rg][1] = sInv[rg * 16 + 8 + lq];
    }

    // ======== pass 2: values (f32 ex2), direct float2 stores ========
    cp_tile(0, sKh0);
    for (int tile = 0; tile < 32; tile++) {
        int m0 = tile * TM;
        __half* cur = (tile & 1) ? sKh1 : sKh0;
        __half* nxt = (tile & 1) ? sKh0 : sKh1;
        CP_WAIT0();
        __syncthreads();
        if (tile < 31) cp_tile((tile + 1) * TM, nxt);
#pragma unroll
        for (int jj = 0; jj < 2; jj++) {
            int j = j0 + jj;
            uint32_t b0[2], b1[2];
#pragma unroll
            for (int kk = 0; kk < 2; kk++) {
                b0[kk] = *(uint32_t*)&cur[(j * 8 + lq) * SKH + kk * 16 + lr * 2];
                b1[kk] = *(uint32_t*)&cur[(j * 8 + lq) * SKH + kk * 16 + lr * 2 + 8];
            }
#pragma unroll
            for (int rg = 0; rg < 4; rg++) {
                float c0 = 0.f, c1 = 0.f, c2 = 0.f, c3 = 0.f;
                mma_f16(c0, c1, c2, c3, aH[rg][0], b0[0], b1[0]);
                mma_f16(c0, c1, c2, c3, aH[rg][1], b0[1], b1[1]);
                float p0 = ex2f(c0) * inv[rg][0];
                float p1 = ex2f(c1) * inv[rg][0];
                float p2 = ex2f(c2) * inv[rg][1];
                float p3 = ex2f(c3) * inv[rg][1];
                size_t base = ((size_t)(b * NPIX + n0 + rg * 16 + lq)) * NPIX
                              + m0 + j * 8 + lr * 2;
                *(float2*)&att[base]            = make_float2(p0, p1);
                *(float2*)&att[base + 8 * NPIX] = make_float2(p2, p3);
            }
        }
        __syncthreads();
    }
}

// ---------------------------------------------------------------------------
// Kernel C: v = Wv·sa_E + bv  (only when gamma != 0 — exact skip otherwise)
// ---------------------------------------------------------------------------
__global__ void v_kernel(const float* __restrict__ saE,
                         const float* __restrict__ Wv,
                         const float* __restrict__ bv,
                         const float* __restrict__ gamma)
{
    if (gamma[0] == 0.f) return;
    int total = BQ * CB * NPIX;
    for (int idx = blockIdx.x * blockDim.x + threadIdx.x; idx < total;
         idx += gridDim.x * blockDim.x) {
        int m  = idx & (NPIX - 1);
        int c  = (idx >> 12) & 255;
        int bb = idx >> 20;
        float s = bv[c];
        for (int cc = 0; cc < 256; cc++)
            s += Wv[c * 256 + cc] * saE[(size_t)(bb * 256 + cc) * NPIX + m];
        g_v[bb][c][m] = s;
    }
}

// ---------------------------------------------------------------------------
// Kernel D: out = gamma*(V·A^T) + sa_E.  gamma==0 -> exact copy (MLP=8)
// ---------------------------------------------------------------------------
__global__ void out_kernel(const float* __restrict__ saE,
                           const float* __restrict__ gamma,
                           float* __restrict__ out,
                           const float* __restrict__ att)
{
    float g = gamma[0];
    const int nvec = (BQ * CB * NPIX) / 4;  // 1048576 float4s
    if (g == 0.f) {
        int i = blockIdx.x * blockDim.x + threadIdx.x;   // 131072 threads
        const int stride = nvec / 8;
        float4 r[8];
#pragma unroll
        for (int k = 0; k < 8; k++) r[k] = ((const float4*)saE)[i + k * stride];
#pragma unroll
        for (int k = 0; k < 8; k++) ((float4*)out)[i + k * stride] = r[k];
    } else {
        for (int i = blockIdx.x * blockDim.x + threadIdx.x; i < nvec;
             i += gridDim.x * blockDim.x) {
            int base = i * 4;
            int n  = base & (NPIX - 1);
            int c  = (base >> 12) & 255;
            int bb = base >> 20;
            float4 e = ((const float4*)saE)[i];
            const float* vrow = &g_v[bb][c][0];
            float rr[4];
#pragma unroll
            for (int jj = 0; jj < 4; jj++) {
                const float* arow = att + (size_t)(bb * NPIX + n + jj) * NPIX;
                float s = 0.f;
                for (int m = 0; m < NPIX; m++) s += vrow[m] * arow[m];
                rr[jj] = g * s + (&e.x)[jj];
            }
            ((float4*)out)[i] = make_float4(rr[0], rr[1], rr[2], rr[3]);
        }
    }
}

// ---------------------------------------------------------------------------
extern "C" void kernel_launch(void* const* d_in, const int* in_sizes, int n_in,
                              void* d_out, int out_size)
{
    const float* saE   = (const float*)d_in[0];
    const float* saD   = (const float*)d_in[1];
    const float* Wq    = (const float*)d_in[2];
    const float* bq    = (const float*)d_in[3];
    const float* Wk    = (const float*)d_in[4];
    const float* bk    = (const float*)d_in[5];
    const float* Wv    = (const float*)d_in[6];
    const float* bv    = (const float*)d_in[7];
    const float* gamma = (const float*)d_in[8];

    float* out = (float*)d_out;
    float* att = out + (size_t)BQ * CB * NPIX;

    size_t smA = (size_t)(64 * 258 + 64 * 64 + 64) * sizeof(float);
    size_t smB = (size_t)(64 * 33 + 8 * 64 + 64) * sizeof(float)
               + (size_t)(2 * 128 * SKH) * sizeof(__half);
    cudaFuncSetAttribute(qk_kernel,   cudaFuncAttributeMaxDynamicSharedMemorySize, (int)smA);
    cudaFuncSetAttribute(attn_kernel, cudaFuncAttributeMaxDynamicSharedMemorySize, (int)smB);

    qk_kernel<<<dim3(64, 4), 256, smA>>>(saD, Wq, bq, Wk, bk);
    attn_kernel<<<dim3(64, 4), 256, smB>>>(att);
    v_kernel<<<1024, 256>>>(saE, Wv, bv, gamma);
    out_kernel<<<512, 256>>>(saE, gamma, out, att);
}

// round 7
// speedup vs baseline: 1.1927x; 1.0917x over previous
#include <cuda_runtime.h>
#include <cuda_fp16.h>
#include <cstdint>

#define NPIX 4096
#define CB   256
#define BQ   4
#define TM   128
#define SKP  32    // packed fp16 K-tile stride in halves (bulk-copy layout)

// Scratch (device globals — no runtime allocation allowed)
__device__ float  g_qk[BQ][32][NPIX];        // q (float), [d][n]
__device__ __half g_kh[BQ][NPIX][32];        // k transposed [m][d], fp16 (1 MB)
__device__ float  g_v[BQ][CB][NPIX];         // only when gamma != 0

#define LOG2E 1.4426950408889634f

__device__ __forceinline__ float ex2f(float x) {
    float r;
    asm("ex2.approx.f32 %0, %1;" : "=f"(r) : "f"(x));
    return r;
}

// ---- bulk-copy + mbarrier primitives ----
__device__ __forceinline__ uint32_t s2u(const void* p) {
    return (uint32_t)__cvta_generic_to_shared(p);
}
__device__ __forceinline__ void mbar_init(uint32_t a, uint32_t cnt) {
    asm volatile("mbarrier.init.shared.b64 [%0], %1;" :: "r"(a), "r"(cnt) : "memory");
}
__device__ __forceinline__ void mbar_expect_tx(uint32_t a, uint32_t bytes) {
    asm volatile("mbarrier.arrive.expect_tx.shared.b64 _, [%0], %1;"
                 :: "r"(a), "r"(bytes) : "memory");
}
__device__ __forceinline__ void bulk_g2s(uint32_t sdst, const void* g,
                                         uint32_t bytes, uint32_t mbar) {
    asm volatile(
        "cp.async.bulk.shared::cta.global.mbarrier::complete_tx::bytes "
        "[%0], [%1], %2, [%3];"
        :: "r"(sdst), "l"(g), "r"(bytes), "r"(mbar) : "memory");
}
__device__ __forceinline__ void mbar_wait(uint32_t a, uint32_t parity) {
    asm volatile(
        "{\n\t.reg .pred P;\n"
        "W%=:\n\tmbarrier.try_wait.parity.acquire.cta.shared::cta.b64 P, [%0], %1, 0x989680;\n"
        "\t@P bra D%=;\n\tbra W%=;\n"
        "D%=:\n\t}\n"
        :: "r"(a), "r"(parity) : "memory");
}

// ---------------------------------------------------------------------------
// Kernel A: q = Wq·sa_D + bq (float, [d][n]), k = Wk·sa_D + bk (fp16, [m][d])
// ---------------------------------------------------------------------------
__global__ void qk_kernel(const float* __restrict__ saD,
                          const float* __restrict__ Wq, const float* __restrict__ bq,
                          const float* __restrict__ Wk, const float* __restrict__ bk)
{
    extern __shared__ float sm[];
    float* sW = sm;                 // 64*258
    float* sX = sm + 64 * 258;      // 64*64
    float* sB = sX + 64 * 64;       // 64

    int b  = blockIdx.y;
    int n0 = blockIdx.x * 64;
    int t  = threadIdx.x;

    for (int i = t; i < 64 * 256; i += 256) {
        int d = i >> 8, c = i & 255;
        sW[d * 258 + c] = (d < 32) ? Wq[d * 256 + c] : Wk[(d - 32) * 256 + c];
    }
    if (t < 64) sB[t] = (t < 32) ? bq[t] : bk[t - 32];
    __syncthreads();

    int ty = t >> 4, tx = t & 15;
    float acc[4][4];
#pragma unroll
    for (int i = 0; i < 4; i++) {
        float bias = sB[ty + 16 * i];
#pragma unroll
        for (int j = 0; j < 4; j++) acc[i][j] = bias;
    }

    for (int c0 = 0; c0 < 256; c0 += 64) {
        __syncthreads();
#pragma unroll
        for (int r = 0; r < 4; r++) {
            int f  = t + 256 * r;
            int cc = f >> 4, nn = (f & 15) << 2;
            *(float4*)&sX[cc * 64 + nn] =
                *(const float4*)&saD[(size_t)(b * 256 + c0 + cc) * NPIX + n0 + nn];
        }
        __syncthreads();
#pragma unroll 4
        for (int cc = 0; cc < 64; cc++) {
            float w0 = sW[(ty     ) * 258 + c0 + cc];
            float w1 = sW[(ty + 16) * 258 + c0 + cc];
            float w2 = sW[(ty + 32) * 258 + c0 + cc];
            float w3 = sW[(ty + 48) * 258 + c0 + cc];
#pragma unroll
            for (int j = 0; j < 4; j++) {
                float x = sX[cc * 64 + tx + 16 * j];
                acc[0][j] += w0 * x; acc[1][j] += w1 * x;
                acc[2][j] += w2 * x; acc[3][j] += w3 * x;
            }
        }
    }
    // q store (float)
#pragma unroll
    for (int i = 0; i < 2; i++)
#pragma unroll
        for (int j = 0; j < 4; j++)
            g_qk[b][ty + 16 * i][n0 + tx + 16 * j] = acc[i][j];

    // fp16 transposed k store: stage [n][d] in smem (reuse sX, padded), out packed
    __syncthreads();
    __half* sT = (__half*)sX;   // 64 x 40 halves (padded stage)
#pragma unroll
    for (int i = 2; i < 4; i++)
#pragma unroll
        for (int j = 0; j < 4; j++)
            sT[(tx + 16 * j) * 40 + ty + 16 * (i - 2)] = __float2half(acc[i][j]);
    __syncthreads();
    {
        int r = t >> 2, p = t & 3;
        uint4 v = *(uint4*)&sT[r * 40 + p * 8];
        *(uint4*)&g_kh[b][n0 + r][p * 8] = v;
    }
}

// ---------------------------------------------------------------------------
// Kernel B: fused energy + softmax + attention, fp16 m16n8k16 both passes.
// K tiles (8KB contiguous) loaded with ONE cp.async.bulk each, mbarrier
// double-buffered; parity carried across both passes. No LDGSTS storm.
// ---------------------------------------------------------------------------
__device__ __forceinline__ void mma_f16(float& c0, float& c1, float& c2, float& c3,
                                        const uint32_t a[4], uint32_t b0, uint32_t b1)
{
    asm volatile(
        "mma.sync.aligned.m16n8k16.row.col.f32.f16.f16.f32 "
        "{%0,%1,%2,%3}, {%4,%5,%6,%7}, {%8,%9}, {%0,%1,%2,%3};"
        : "+f"(c0), "+f"(c1), "+f"(c2), "+f"(c3)
        : "r"(a[0]), "r"(a[1]), "r"(a[2]), "r"(a[3]), "r"(b0), "r"(b1));
}

__device__ __forceinline__ uint32_t packh(float lo, float hi) {
    __half2 h = __floats2half2_rn(lo, hi);
    return *(uint32_t*)&h;
}

__global__ __launch_bounds__(256, 2) void attn_kernel(float* __restrict__ att)
{
    extern __shared__ float sm[];
    float*  sQ   = sm;                            // 64*33 floats (8448 B)
    __half* sK   = (__half*)(sm + 64 * 33);       // 2 bufs x 128*SKP halves (16 KB)
    float*  sSum = (float*)(sK + 2 * 128 * SKP);  // 8*64
    float*  sInv = sSum + 8 * 64;                 // 64
    uint64_t* mbars = (uint64_t*)(sInv + 64);     // 2 mbarriers (8B aligned)

    int b  = blockIdx.y;
    int n0 = blockIdx.x * 64;
    int t  = threadIdx.x, w = t >> 5, l = t & 31;
    int lq = l >> 2, lr = l & 3;
    int j0 = 2 * w;

    const float*  qg  = &g_qk[b][0][0];
    const __half* khg = &g_kh[b][0][0];

    uint32_t mb0 = s2u(&mbars[0]), mb1 = s2u(&mbars[1]);
    uint32_t skbase = s2u(sK);

    if (t == 0) { mbar_init(mb0, 1); mbar_init(mb1, 1); }

    // Q tile [64 n][32 d], transposed, pre-scaled by log2e
    for (int i = t; i < 64 * 32; i += 256) {
        int n = i & 63, d = i >> 6;
        sQ[n * 33 + d] = qg[(size_t)d * NPIX + n0 + n] * LOG2E;
    }
    __syncthreads();   // covers mbarrier init + sQ

    auto issue = [&](int tile) {
        if (t == 0) {
            uint32_t mb = (tile & 1) ? mb1 : mb0;
            mbar_expect_tx(mb, 8192);
            bulk_g2s(skbase + (tile & 1) * 8192, khg + (size_t)tile * TM * SKP,
                     8192, mb);
        }
    };

    int ph0 = 0, ph1 = 0;
    issue(0); issue(1);

    // A fragments fp16: 4 row-groups x 2 k16-chunks x 4 regs (used by both passes)
    uint32_t aH[4][2][4];
#pragma unroll
    for (int rg = 0; rg < 4; rg++) {
        int r = rg * 16 + lq;
#pragma unroll
        for (int kk = 0; kk < 2; kk++) {
            int c = kk * 16 + lr * 2;
            aH[rg][kk][0] = packh(sQ[r * 33 + c],           sQ[r * 33 + c + 1]);
            aH[rg][kk][1] = packh(sQ[(r + 8) * 33 + c],     sQ[(r + 8) * 33 + c + 1]);
            aH[rg][kk][2] = packh(sQ[r * 33 + c + 8],       sQ[r * 33 + c + 9]);
            aH[rg][kk][3] = packh(sQ[(r + 8) * 33 + c + 8], sQ[(r + 8) * 33 + c + 9]);
        }
    }

    // ======== pass 1: denominators via f16x2 exp2 ========
    float s[4][2];
#pragma unroll
    for (int rg = 0; rg < 4; rg++) s[rg][0] = s[rg][1] = 0.f;

    for (int tile = 0; tile < 32; tile++) {
        int bsel = tile & 1;
        if (bsel) { mbar_wait(mb1, ph1); ph1 ^= 1; }
        else      { mbar_wait(mb0, ph0); ph0 ^= 1; }
        __half* cur = sK + bsel * 128 * SKP;

        __half2 ha[4][2];
#pragma unroll
        for (int rg = 0; rg < 4; rg++) {
            ha[rg][0] = __floats2half2_rn(0.f, 0.f);
            ha[rg][1] = __floats2half2_rn(0.f, 0.f);
        }
#pragma unroll
        for (int jj = 0; jj < 2; jj++) {
            int j = j0 + jj;
            uint32_t b0[2], b1[2];
#pragma unroll
            for (int kk = 0; kk < 2; kk++) {
                b0[kk] = *(uint32_t*)&cur[(j * 8 + lq) * SKP + kk * 16 + lr * 2];
                b1[kk] = *(uint32_t*)&cur[(j * 8 + lq) * SKP + kk * 16 + lr * 2 + 8];
            }
#pragma unroll
            for (int rg = 0; rg < 4; rg++) {
                float c0 = 0.f, c1 = 0.f, c2 = 0.f, c3 = 0.f;
                mma_f16(c0, c1, c2, c3, aH[rg][0], b0[0], b1[0]);
                mma_f16(c0, c1, c2, c3, aH[rg][1], b0[1], b1[1]);
                ha[rg][0] = __hadd2(ha[rg][0], h2exp2(__floats2half2_rn(c0, c1)));
                ha[rg][1] = __hadd2(ha[rg][1], h2exp2(__floats2half2_rn(c2, c3)));
            }
        }
#pragma unroll
        for (int rg = 0; rg < 4; rg++) {
            float2 f0 = __half22float2(ha[rg][0]);
            float2 f1 = __half22float2(ha[rg][1]);
            s[rg][0] += f0.x + f0.y;
            s[rg][1] += f1.x + f1.y;
        }
        __syncthreads();               // all warps done with this buffer
        if (tile + 2 < 32) issue(tile + 2);
    }
#pragma unroll
    for (int rg = 0; rg < 4; rg++)
#pragma unroll
        for (int h = 0; h < 2; h++) {
            s[rg][h] += __shfl_xor_sync(0xffffffffu, s[rg][h], 1);
            s[rg][h] += __shfl_xor_sync(0xffffffffu, s[rg][h], 2);
        }
    if (lr == 0)
#pragma unroll
        for (int rg = 0; rg < 4; rg++) {
            sSum[w * 64 + rg * 16 + lq]     = s[rg][0];
            sSum[w * 64 + rg * 16 + 8 + lq] = s[rg][1];
        }
    __syncthreads();
    if (t < 64) {
        float tot = 0.f;
#pragma unroll
        for (int ww = 0; ww < 8; ww++) tot += sSum[ww * 64 + t];
        sInv[t] = 1.f / tot;
    }
    __syncthreads();

    float inv[4][2];
#pragma unroll
    for (int rg = 0; rg < 4; rg++) {
        inv[rg][0] = sInv[rg * 16 + lq];
        inv[rg][1] = sInv[rg * 16 + 8 + lq];
    }

    // ======== pass 2: values (f32 ex2), direct float2 stores ========
    issue(0); issue(1);
    for (int tile = 0; tile < 32; tile++) {
        int m0 = tile * TM;
        int bsel = tile & 1;
        if (bsel) { mbar_wait(mb1, ph1); ph1 ^= 1; }
        else      { mbar_wait(mb0, ph0); ph0 ^= 1; }
        __half* cur = sK + bsel * 128 * SKP;
#pragma unroll
        for (int jj = 0; jj < 2; jj++) {
            int j = j0 + jj;
            uint32_t b0[2], b1[2];
#pragma unroll
            for (int kk = 0; kk < 2; kk++) {
                b0[kk] = *(uint32_t*)&cur[(j * 8 + lq) * SKP + kk * 16 + lr * 2];
                b1[kk] = *(uint32_t*)&cur[(j * 8 + lq) * SKP + kk * 16 + lr * 2 + 8];
            }
#pragma unroll
            for (int rg = 0; rg < 4; rg++) {
                float c0 = 0.f, c1 = 0.f, c2 = 0.f, c3 = 0.f;
                mma_f16(c0, c1, c2, c3, aH[rg][0], b0[0], b1[0]);
                mma_f16(c0, c1, c2, c3, aH[rg][1], b0[1], b1[1]);
                float p0 = ex2f(c0) * inv[rg][0];
                float p1 = ex2f(c1) * inv[rg][0];
                float p2 = ex2f(c2) * inv[rg][1];
                float p3 = ex2f(c3) * inv[rg][1];
                size_t base = ((size_t)(b * NPIX + n0 + rg * 16 + lq)) * NPIX
                              + m0 + j * 8 + lr * 2;
                *(float2*)&att[base]            = make_float2(p0, p1);
                *(float2*)&att[base + 8 * NPIX] = make_float2(p2, p3);
            }
        }
        __syncthreads();
        if (tile + 2 < 32) issue(tile + 2);
    }
}

// ---------------------------------------------------------------------------
// Kernel C: v = Wv·sa_E + bv  (only when gamma != 0 — exact skip otherwise)
// ---------------------------------------------------------------------------
__global__ void v_kernel(const float* __restrict__ saE,
                         const float* __restrict__ Wv,
                         const float* __restrict__ bv,
                         const float* __restrict__ gamma)
{
    if (gamma[0] == 0.f) return;
    int total = BQ * CB * NPIX;
    for (int idx = blockIdx.x * blockDim.x + threadIdx.x; idx < total;
         idx += gridDim.x * blockDim.x) {
        int m  = idx & (NPIX - 1);
        int c  = (idx >> 12) & 255;
        int bb = idx >> 20;
        float s = bv[c];
        for (int cc = 0; cc < 256; cc++)
            s += Wv[c * 256 + cc] * saE[(size_t)(bb * 256 + cc) * NPIX + m];
        g_v[bb][c][m] = s;
    }
}

// ---------------------------------------------------------------------------
// Kernel D: out = gamma*(V·A^T) + sa_E.  gamma==0 -> exact copy (MLP=8)
// ---------------------------------------------------------------------------
__global__ void out_kernel(const float* __restrict__ saE,
                           const float* __restrict__ gamma,
                           float* __restrict__ out,
                           const float* __restrict__ att)
{
    float g = gamma[0];
    const int nvec = (BQ * CB * NPIX) / 4;  // 1048576 float4s
    if (g == 0.f) {
        int i = blockIdx.x * blockDim.x + threadIdx.x;   // 131072 threads
        const int stride = nvec / 8;
        float4 r[8];
#pragma unroll
        for (int k = 0; k < 8; k++) r[k] = ((const float4*)saE)[i + k * stride];
#pragma unroll
        for (int k = 0; k < 8; k++) ((float4*)out)[i + k * stride] = r[k];
    } else {
        for (int i = blockIdx.x * blockDim.x + threadIdx.x; i < nvec;
             i += gridDim.x * blockDim.x) {
            int base = i * 4;
            int n  = base & (NPIX - 1);
            int c  = (base >> 12) & 255;
            int bb = base >> 20;
            float4 e = ((const float4*)saE)[i];
            const float* vrow = &g_v[bb][c][0];
            float rr[4];
#pragma unroll
            for (int jj = 0; jj < 4; jj++) {
                const float* arow = att + (size_t)(bb * NPIX + n + jj) * NPIX;
                float s = 0.f;
                for (int m = 0; m < NPIX; m++) s += vrow[m] * arow[m];
                rr[jj] = g * s + (&e.x)[jj];
            }
            ((float4*)out)[i] = make_float4(rr[0], rr[1], rr[2], rr[3]);
        }
    }
}

// ---------------------------------------------------------------------------
extern "C" void kernel_launch(void* const* d_in, const int* in_sizes, int n_in,
                              void* d_out, int out_size)
{
    const float* saE   = (const float*)d_in[0];
    const float* saD   = (const float*)d_in[1];
    const float* Wq    = (const float*)d_in[2];
    const float* bq    = (const float*)d_in[3];
    const float* Wk    = (const float*)d_in[4];
    const float* bk    = (const float*)d_in[5];
    const float* Wv    = (const float*)d_in[6];
    const float* bv    = (const float*)d_in[7];
    const float* gamma = (const float*)d_in[8];

    float* out = (float*)d_out;
    float* att = out + (size_t)BQ * CB * NPIX;

    size_t smA = (size_t)(64 * 258 + 64 * 64 + 64) * sizeof(float);
    size_t smB = (size_t)(64 * 33 + 8 * 64 + 64) * sizeof(float)
               + (size_t)(2 * 128 * SKP) * sizeof(__half)
               + 4 * sizeof(uint64_t);   // mbarriers + pad
    cudaFuncSetAttribute(qk_kernel,   cudaFuncAttributeMaxDynamicSharedMemorySize, (int)smA);
    cudaFuncSetAttribute(attn_kernel, cudaFuncAttributeMaxDynamicSharedMemorySize, (int)smB);

    qk_kernel<<<dim3(64, 4), 256, smA>>>(saD, Wq, bq, Wk, bk);
    attn_kernel<<<dim3(64, 4), 256, smB>>>(att);
    v_kernel<<<1024, 256>>>(saE, Wv, bv, gamma);
    out_kernel<<<512, 256>>>(saE, gamma, out, att);
}